// round 1
// baseline (speedup 1.0000x reference)
#include <cuda_runtime.h>
#include <stdint.h>

#define HH 1024
#define WW 1024
#define BB 8
#define CC 3
#define HW (HH*WW)
#define RMAX 8
#define SPITCH 1040   // 1024 + 16 right pad (255-filled) so xA=x+2r never OOB

// scratch (allocation-free rule: __device__ globals)
__device__ float g_cnt[2u*BB*HW];            // [view*B+b][y][x]  (64 MB)
__device__ float g_segsum[16*8*4*WW];        // [vb][seg][plane][x] (2 MB)

// ---------- float4 helpers ----------
__device__ __forceinline__ float4 f4add(float4 a, float4 b){
    return make_float4(a.x+b.x, a.y+b.y, a.z+b.z, a.w+b.w);
}
__device__ __forceinline__ float4 f4sub(float4 a, float4 b){
    return make_float4(a.x-b.x, a.y-b.y, a.z-b.z, a.w-b.w);
}

__device__ __forceinline__ void addpix(float4& a, float s,
                                       const float* __restrict__ imgb,
                                       int row, int col) {
    const float* p = imgb + (size_t)row*WW + col;
    a.x += s;
    a.y += s * __ldg(p);
    a.z += s * __ldg(p + HW);
    a.w += s * __ldg(p + 2*HW);
}

__device__ __forceinline__ float4 warp_iscan4(float4 v) {
    int lane = threadIdx.x & 31;
    #pragma unroll
    for (int o = 1; o < 32; o <<= 1) {
        float ax = __shfl_up_sync(0xffffffffu, v.x, o);
        float ay = __shfl_up_sync(0xffffffffu, v.y, o);
        float az = __shfl_up_sync(0xffffffffu, v.z, o);
        float aw = __shfl_up_sync(0xffffffffu, v.w, o);
        if (lane >= o) { v.x += ax; v.y += ay; v.z += az; v.w += aw; }
    }
    return v;
}

// ---------- K1: delta gather + row (x) inclusive scan ----------
__global__ __launch_bounds__(256)
void k_rowscan(const float* __restrict__ image,
               const float* __restrict__ depth,
               float* __restrict__ out) {
    __shared__ uint8_t sR[16][SPITCH];
    __shared__ float4 wtl[8], wtr[8];

    const int y   = blockIdx.x;
    const int b   = blockIdx.y;
    const int tid = threadIdx.x;

    // load R for absolute rows [y-8, y+7]; invalid rows/cols -> 255
    const float* drow = depth + (size_t)b*HW;
    for (int i = tid; i < 16*SPITCH; i += 256) {
        int rr  = i / SPITCH;
        int col = i - rr*SPITCH;
        int ar  = y - 8 + rr;
        uint8_t v = 255;
        if (col < WW && ar >= 0 && ar < HH)
            v = (uint8_t)(int)drow[(size_t)ar*WW + col];   // floor, depth>=0
        sR[rr][col] = v;
    }
    __syncthreads();

    const float* imgb = image + (size_t)b*CC*HW;

    float4 pl[4], pr[4];
    float4 accl = make_float4(0,0,0,0), accr = make_float4(0,0,0,0);

    for (int i = 0; i < 4; ++i) {
        const int x = 4*tid + i;
        float4 dl = make_float4(0,0,0,0), dr = make_float4(0,0,0,0);

        if (y > 0 && x > 0) {
            // ---- fast interior path ----
            #pragma unroll
            for (int r = 0; r < RMAX; ++r) {
                const int ti = 8 + r, bi = 7 - r;
                const int trow = y + r, brow = y - r - 1;
                const int xA = x + 2*r;     // padded smem: safe up to 1039
                const int xB = x - 1;
                const int xD = x - 2*r - 1;
                // left view
                if (sR[ti][xA] == r) addpix(dl,  1.f, imgb, trow, xA);
                if (sR[ti][xB] == r) addpix(dl, -1.f, imgb, trow, xB);
                if (sR[bi][xA] == r) addpix(dl, -1.f, imgb, brow, xA);
                if (sR[bi][xB] == r) addpix(dl,  1.f, imgb, brow, xB);
                // right view
                if (sR[ti][x]  == r) addpix(dr,  1.f, imgb, trow, x);
                if (sR[bi][x]  == r) addpix(dr, -1.f, imgb, brow, x);
                if (xD >= 0) {
                    if (sR[ti][xD] == r) addpix(dr, -1.f, imgb, trow, xD);
                    if (sR[bi][xD] == r) addpix(dr,  1.f, imgb, brow, xD);
                }
            }
        } else {
            // ---- generic border path (handles y==0 / x==0 clamp sums) ----
            for (int r = 0; r < RMAX; ++r) {
                const int t0 = (y > 0) ? y + r : 0;
                const int t1 = (y > 0) ? y + r : r;
                const int brow = y - r - 1;
                const int a0 = (x > 0) ? x + 2*r : 0;
                const int a1 = (x > 0) ? x + 2*r : 2*r;
                const int xB = x - 1;
                const int xD = x - 2*r - 1;
                for (int yy = t0; yy <= t1; ++yy) {
                    const int idx = yy - y + 8;
                    for (int a = a0; a <= a1; ++a)
                        if (a < WW && sR[idx][a] == r) addpix(dl,  1.f, imgb, yy, a);
                    if (xB >= 0 && sR[idx][xB] == r)   addpix(dl, -1.f, imgb, yy, xB);
                    if (sR[idx][x] == r)               addpix(dr,  1.f, imgb, yy, x);
                    if (xD >= 0 && sR[idx][xD] == r)   addpix(dr, -1.f, imgb, yy, xD);
                }
                if (brow >= 0) {
                    const int idx = 7 - r;
                    for (int a = a0; a <= a1; ++a)
                        if (a < WW && sR[idx][a] == r) addpix(dl, -1.f, imgb, brow, a);
                    if (xB >= 0 && sR[idx][xB] == r)   addpix(dl,  1.f, imgb, brow, xB);
                    if (sR[idx][x] == r)               addpix(dr, -1.f, imgb, brow, x);
                    if (xD >= 0 && sR[idx][xD] == r)   addpix(dr,  1.f, imgb, brow, xD);
                }
            }
        }
        accl = f4add(accl, dl);  pl[i] = accl;
        accr = f4add(accr, dr);  pr[i] = accr;
    }

    // ---- block-wide inclusive scan along x ----
    const int lane = tid & 31, wid = tid >> 5;
    float4 tl = pl[3], tr = pr[3];
    float4 il = warp_iscan4(tl);
    float4 ir = warp_iscan4(tr);
    if (lane == 31) { wtl[wid] = il; wtr[wid] = ir; }
    __syncthreads();
    if (tid == 0) {
        float4 s = make_float4(0,0,0,0);
        for (int w = 0; w < 8; ++w) { float4 t = wtl[w]; wtl[w] = s; s = f4add(s, t); }
        s = make_float4(0,0,0,0);
        for (int w = 0; w < 8; ++w) { float4 t = wtr[w]; wtr[w] = s; s = f4add(s, t); }
    }
    __syncthreads();
    float4 offl = f4add(wtl[wid], f4sub(il, tl));
    float4 offr = f4add(wtr[wid], f4sub(ir, tr));

    float4 rl[4], rr[4];
    #pragma unroll
    for (int i = 0; i < 4; ++i) { rl[i] = f4add(pl[i], offl); rr[i] = f4add(pr[i], offr); }

    // ---- stores: cnt -> g_cnt, channels -> d_out planes ----
    const int vbL = b, vbR = BB + b;               // view*B + b
    const size_t rowoff = (size_t)y*WW + 4*tid;

    *(float4*)(g_cnt + (size_t)vbL*HW + rowoff) =
        make_float4(rl[0].x, rl[1].x, rl[2].x, rl[3].x);
    *(float4*)(g_cnt + (size_t)vbR*HW + rowoff) =
        make_float4(rr[0].x, rr[1].x, rr[2].x, rr[3].x);

    float* oL = out + (size_t)vbL*CC*HW + rowoff;
    float* oR = out + (size_t)vbR*CC*HW + rowoff;
    *(float4*)(oL)          = make_float4(rl[0].y, rl[1].y, rl[2].y, rl[3].y);
    *(float4*)(oL + HW)     = make_float4(rl[0].z, rl[1].z, rl[2].z, rl[3].z);
    *(float4*)(oL + 2*HW)   = make_float4(rl[0].w, rl[1].w, rl[2].w, rl[3].w);
    *(float4*)(oR)          = make_float4(rr[0].y, rr[1].y, rr[2].y, rr[3].y);
    *(float4*)(oR + HW)     = make_float4(rr[0].z, rr[1].z, rr[2].z, rr[3].z);
    *(float4*)(oR + 2*HW)   = make_float4(rr[0].w, rr[1].w, rr[2].w, rr[3].w);
}

// ---------- K2a: per-segment column sums (4 planes per vb) ----------
__global__ __launch_bounds__(128)
void k_colsum(const float* __restrict__ out) {
    const int vb  = blockIdx.z;                      // 0..15 = view*8+b
    const int seg = blockIdx.y;                      // 0..7
    const int xc  = blockIdx.x*512 + threadIdx.x*4;

    const float* p0 = g_cnt + (size_t)vb*HW + xc;
    const float* p1 = out   + ((size_t)vb*CC + 0)*HW + xc;
    const float* p2 = p1 + HW;
    const float* p3 = p1 + 2*HW;

    float4 s0 = make_float4(0,0,0,0), s1 = s0, s2 = s0, s3 = s0;
    const int y0 = seg*128;
    #pragma unroll 4
    for (int yy = 0; yy < 128; ++yy) {
        const size_t o = (size_t)(y0 + yy)*WW;
        s0 = f4add(s0, __ldg((const float4*)(p0 + o)));
        s1 = f4add(s1, __ldg((const float4*)(p1 + o)));
        s2 = f4add(s2, __ldg((const float4*)(p2 + o)));
        s3 = f4add(s3, __ldg((const float4*)(p3 + o)));
    }
    float* ss = g_segsum + (size_t)((vb*8 + seg)*4)*WW + xc;
    *(float4*)(ss + 0*WW) = s0;
    *(float4*)(ss + 1*WW) = s1;
    *(float4*)(ss + 2*WW) = s2;
    *(float4*)(ss + 3*WW) = s3;
}

// ---------- K2c: column scan (seeded by segment offsets) + finalize ----------
__global__ __launch_bounds__(128)
void k_colscan_final(float* __restrict__ out) {
    const int vb  = blockIdx.z;
    const int seg = blockIdx.y;
    const int xc  = blockIdx.x*512 + threadIdx.x*4;

    float4 r0 = make_float4(0,0,0,0), r1 = r0, r2 = r0, r3 = r0;
    for (int s = 0; s < seg; ++s) {
        const float* ss = g_segsum + (size_t)((vb*8 + s)*4)*WW + xc;
        r0 = f4add(r0, __ldg((const float4*)(ss + 0*WW)));
        r1 = f4add(r1, __ldg((const float4*)(ss + 1*WW)));
        r2 = f4add(r2, __ldg((const float4*)(ss + 2*WW)));
        r3 = f4add(r3, __ldg((const float4*)(ss + 3*WW)));
    }

    const float* p0 = g_cnt + (size_t)vb*HW + xc;
    float* p1 = out + ((size_t)vb*CC + 0)*HW + xc;
    float* p2 = p1 + HW;
    float* p3 = p1 + 2*HW;

    const int y0 = seg*128;
    #pragma unroll 2
    for (int yy = 0; yy < 128; ++yy) {
        const size_t o = (size_t)(y0 + yy)*WW;
        r0 = f4add(r0, __ldg((const float4*)(p0 + o)));
        r1 = f4add(r1, __ldg((const float4*)(p1 + o)));
        r2 = f4add(r2, __ldg((const float4*)(p2 + o)));
        r3 = f4add(r3, __ldg((const float4*)(p3 + o)));

        float4 inv;
        inv.x = __fdividef(1.0f, fmaxf(r0.x, 1.0f));
        inv.y = __fdividef(1.0f, fmaxf(r0.y, 1.0f));
        inv.z = __fdividef(1.0f, fmaxf(r0.z, 1.0f));
        inv.w = __fdividef(1.0f, fmaxf(r0.w, 1.0f));

        *(float4*)(p1 + o) = make_float4(__saturatef(r1.x*inv.x), __saturatef(r1.y*inv.y),
                                         __saturatef(r1.z*inv.z), __saturatef(r1.w*inv.w));
        *(float4*)(p2 + o) = make_float4(__saturatef(r2.x*inv.x), __saturatef(r2.y*inv.y),
                                         __saturatef(r2.z*inv.z), __saturatef(r2.w*inv.w));
        *(float4*)(p3 + o) = make_float4(__saturatef(r3.x*inv.x), __saturatef(r3.y*inv.y),
                                         __saturatef(r3.z*inv.z), __saturatef(r3.w*inv.w));
    }
}

extern "C" void kernel_launch(void* const* d_in, const int* in_sizes, int n_in,
                              void* d_out, int out_size) {
    const float* image = (const float*)d_in[0];   // (8,3,1024,1024) f32
    const float* depth = (const float*)d_in[1];   // (8,1024,1024)   f32
    float* out = (float*)d_out;                   // [left(8,3,H,W), right(8,3,H,W)]

    k_rowscan<<<dim3(HH, BB), 256>>>(image, depth, out);
    k_colsum<<<dim3(2, 8, 16), 128>>>(out);
    k_colscan_final<<<dim3(2, 8, 16), 128>>>(out);
}